// round 4
// baseline (speedup 1.0000x reference)
#include <cuda_runtime.h>
#include <cuda_fp16.h>

// InterpolateSparse2d on GB300 — round 4: fused persistent producer/consumer.
// R1: NCHW gather is L1-wavefront-bound -> channels-last scratch.
// R2/R3: transpose(fp16 scratch) 75us + gather 30us; transpose at HBM ceiling.
// R4: fuse. Scratch becomes a 4-batch L2-resident ring (39MB); gather reads hit
//     L2 and overlap with transpose streaming. Ordered work-queue, persistent
//     grid with guaranteed full residency -> deadlock-free dependency spins.

#define BB 16
#define CC 64
#define HX 240
#define WX 320
#define NN 20000
#define HW (HX * WX)

#define NBUF 4                     // scratch ring depth (batches)
#define ITEMS_T 2400               // transpose chunks per batch (32 pixels each)
#define ITEMS_G 625                // gather items per batch (32 points each)
#define ITEMS_B (ITEMS_T + ITEMS_G)
#define TOTAL_ITEMS (BB * ITEMS_B)

#define GRID_BLOCKS (148 * 6)      // all-resident persistent grid

// 4 batches * 76800 pixels * 128B = 39.3 MB — L2-resident ring.
__device__ uint4 g_scr[(long long)NBUF * HW * 8];

__device__ int g_ticket;
__device__ int g_tdone[BB];
__device__ int g_gdone[BB];

__global__ void init_counters()
{
    int t = threadIdx.x;
    if (t == 0) g_ticket = 0;
    if (t < BB) { g_tdone[t] = 0; g_gdone[t] = 0; }
}

__global__ void __launch_bounds__(256, 6)
fused_interp(const float* __restrict__ x,
             const float* __restrict__ pos,
             const int* __restrict__ Hp,
             const int* __restrict__ Wp,
             float* __restrict__ out)
{
    __shared__ float tile[64 * 33];    // transpose staging
    __shared__ int s_item;

    const int tid = threadIdx.x;

    while (true) {
        if (tid == 0) s_item = atomicAdd(&g_ticket, 1);
        __syncthreads();
        int item = s_item;
        if (item >= TOTAL_ITEMS) break;

        int k  = item / ITEMS_B;           // batch
        int wi = item - k * ITEMS_B;

        if (wi < ITEMS_T) {
            // ---------------- transpose chunk: 32 pixels x 64 ch ----------------
            // WAR: ring slot (k&3) must be drained by gather of batch k-NBUF.
            if (k >= NBUF) {
                if (tid == 0) {
                    while (atomicAdd(&g_gdone[k - NBUF], 0) < ITEMS_G) __nanosleep(64);
                    __threadfence();
                }
                __syncthreads();
            }

            int p0 = wi * 32;
            int pl = tid & 31;             // pixel lane
            int c0 = tid >> 5;             // 0..7

            const float* src = x + (long long)k * CC * HW + p0;
            #pragma unroll
            for (int i = 0; i < 8; i++) {
                int c = c0 + i * 8;
                tile[c * 33 + pl] = __ldg(src + (long long)c * HW + pl);
            }
            __syncthreads();

            int c2 = tid & 31;             // half2 index (channels 2c2, 2c2+1)
            int pg = tid >> 5;             // 0..7
            __half2* dst = (__half2*)(g_scr + ((long long)(k & (NBUF - 1)) * HW + p0) * 8);
            #pragma unroll
            for (int i = 0; i < 4; i++) {
                int p = pg + i * 8;
                float lo = tile[(2 * c2)     * 33 + p];
                float hi = tile[(2 * c2 + 1) * 33 + p];
                dst[p * 32 + c2] = __floats2half2_rn(lo, hi);
            }
            __syncthreads();               // all stores issued; also protects tile reuse
            if (tid == 0) {
                __threadfence();           // publish scratch writes (cumulative release)
                atomicAdd(&g_tdone[k], 1);
            }
        } else {
            // ---------------- gather item: 32 points x 64 ch ----------------
            if (tid == 0) {
                while (atomicAdd(&g_tdone[k], 0) < ITEMS_T) __nanosleep(64);
                __threadfence();           // acquire
            }
            __syncthreads();

            int g = wi - ITEMS_T;
            int lane8 = tid & 7;           // 8 channels per lane
            int p     = g * 32 + (tid >> 3);
            long long pn = (long long)k * NN + p;

            float posx = pos[pn * 2 + 0];
            float posy = pos[pn * 2 + 1];
            float Wf = (float)(*Wp);
            float Hf = (float)(*Hp);

            float px = posx * (float)(WX - 1) / Wf;
            float py = posy * (float)(HX - 1) / Hf;

            int x0 = (int)floorf(px);
            int y0 = (int)floorf(py);
            x0 = min(max(x0, 0), WX - 1);
            y0 = min(max(y0, 0), HX - 1);
            int x1 = min(x0 + 1, WX - 1);
            int y1 = min(y0 + 1, HX - 1);

            float x0f = (float)x0, x1f = (float)x1;
            float y0f = (float)y0, y1f = (float)y1;

            float wa = (x1f - px) * (y1f - py);
            float wb = (x1f - px) * (py - y0f);
            float wc = (px - x0f) * (y1f - py);
            float wd = (px - x0f) * (py - y0f);

            long long bufb = (long long)(k & (NBUF - 1)) * HW;
            long long i00 = (bufb + y0 * WX + x0) * 8 + lane8;
            long long i01 = (bufb + y0 * WX + x1) * 8 + lane8;
            long long i10 = (bufb + y1 * WX + x0) * 8 + lane8;
            long long i11 = (bufb + y1 * WX + x1) * 8 + lane8;

            uint4 A  = __ldg(g_scr + i00);
            uint4 Bv = __ldg(g_scr + i10);
            uint4 Cv = __ldg(g_scr + i01);
            uint4 D  = __ldg(g_scr + i11);

            float r[8];
            const unsigned* au = (const unsigned*)&A;
            const unsigned* bu = (const unsigned*)&Bv;
            const unsigned* cu = (const unsigned*)&Cv;
            const unsigned* du = (const unsigned*)&D;
            #pragma unroll
            for (int j = 0; j < 4; j++) {
                float2 fa = __half22float2(*(const __half2*)&au[j]);
                float2 fb = __half22float2(*(const __half2*)&bu[j]);
                float2 fc = __half22float2(*(const __half2*)&cu[j]);
                float2 fd = __half22float2(*(const __half2*)&du[j]);
                r[2 * j + 0] = wa * fa.x + wb * fb.x + wc * fc.x + wd * fd.x;
                r[2 * j + 1] = wa * fa.y + wb * fb.y + wc * fc.y + wd * fd.y;
            }

            float4* o = (float4*)out;
            long long ob = pn * 16 + lane8 * 2;
            o[ob + 0] = make_float4(r[0], r[1], r[2], r[3]);
            o[ob + 1] = make_float4(r[4], r[5], r[6], r[7]);

            __syncthreads();               // all reads of ring slot complete
            if (tid == 0) {
                __threadfence();
                atomicAdd(&g_gdone[k], 1); // release ring slot for batch k+NBUF
            }
        }
    }
}

extern "C" void kernel_launch(void* const* d_in, const int* in_sizes, int n_in,
                              void* d_out, int out_size)
{
    const float* x   = (const float*)d_in[0];
    const float* pos = (const float*)d_in[1];
    const int*   Hp  = (const int*)d_in[2];
    const int*   Wp  = (const int*)d_in[3];
    float* out = (float*)d_out;

    init_counters<<<1, 32>>>();
    fused_interp<<<GRID_BLOCKS, 256>>>(x, pos, Hp, Wp, out);
}

// round 6
// speedup vs baseline: 1.4784x; 1.4784x over previous
#include <cuda_runtime.h>
#include <cuda_fp16.h>

// InterpolateSparse2d on GB300 — round 5: fused v2, phase-barriered.
// R4 failed (201us): ordered ticket queue left ~70% of blocks idle-spinning on
// per-batch dependencies. v2 uses batch-pair PHASES with a monotone grid
// barrier: every block always has statically-assigned work; transpose (DRAM)
// and gather (L2) items interleave within each phase. Scratch = 4-batch fp16
// ring (39MB) that stays L2-resident, so gather corner reads are L2 hits and
// the scratch round-trip to DRAM (R3: 157MB write + ~130MB read) mostly
// disappears.

#define BB 16
#define CC 64
#define HX 240
#define WX 320
#define NN 20000
#define HW (HX * WX)

#define NBUF 4                       // ring slots (batches)
#define CH_T 2400                    // transpose chunks per batch (32 px each)
#define CH_G 625                     // gather chunks per batch (32 pts each)

#define GRID_BLOCKS (148 * 6)        // all-resident persistent grid
#define NPHASE 9                     // 8 batch pairs pipelined + drain

// Ring: 4 batches * 76800 px * 128B = 39.3 MB (target: L2-resident).
__device__ uint4 g_scr[(long long)NBUF * HW * 8];
__device__ unsigned g_arrive;        // monotone barrier arrival counter

__global__ void init_counters() { if (threadIdx.x == 0) g_arrive = 0; }

// ---------------------------------------------------------------------------
__device__ __forceinline__ void do_transpose_chunk(const float* __restrict__ x,
                                                   int b, int chunk, int tid,
                                                   float* tile)
{
    int p0 = chunk * 32;
    int pl = tid & 31;               // pixel lane
    int c0 = tid >> 5;               // 0..7

    const float* src = x + (long long)b * CC * HW + p0;
    #pragma unroll
    for (int i = 0; i < 8; i++) {
        int c = c0 + i * 8;
        tile[c * 33 + pl] = __ldg(src + (long long)c * HW + pl);   // 128B/warp
    }
    __syncthreads();

    int c2 = tid & 31;               // half2 index (channels 2c2, 2c2+1)
    int pg = tid >> 5;               // 0..7
    __half2* dst = (__half2*)(g_scr + ((long long)(b & (NBUF - 1)) * HW + p0) * 8);
    #pragma unroll
    for (int i = 0; i < 4; i++) {
        int p = pg + i * 8;
        float lo = tile[(2 * c2)     * 33 + p];
        float hi = tile[(2 * c2 + 1) * 33 + p];
        dst[p * 32 + c2] = __floats2half2_rn(lo, hi);
    }
    __syncthreads();                 // tile reuse safety for next item
}

__device__ __forceinline__ void do_gather_chunk(const float* __restrict__ pos,
                                                float Wf, float Hf,
                                                int b, int chunk, int tid,
                                                float* __restrict__ out)
{
    int lane8 = tid & 7;             // 8 channels per lane
    int p     = chunk * 32 + (tid >> 3);
    long long pn = (long long)b * NN + p;

    float posx = pos[pn * 2 + 0];
    float posy = pos[pn * 2 + 1];

    float px = posx * (float)(WX - 1) / Wf;
    float py = posy * (float)(HX - 1) / Hf;

    int x0 = (int)floorf(px);
    int y0 = (int)floorf(py);
    x0 = min(max(x0, 0), WX - 1);
    y0 = min(max(y0, 0), HX - 1);
    int x1 = min(x0 + 1, WX - 1);
    int y1 = min(y0 + 1, HX - 1);

    float x0f = (float)x0, x1f = (float)x1;
    float y0f = (float)y0, y1f = (float)y1;

    float wa = (x1f - px) * (y1f - py);
    float wb = (x1f - px) * (py - y0f);
    float wc = (px - x0f) * (y1f - py);
    float wd = (px - x0f) * (py - y0f);

    long long bufb = (long long)(b & (NBUF - 1)) * HW;
    long long i00 = (bufb + y0 * WX + x0) * 8 + lane8;
    long long i01 = (bufb + y0 * WX + x1) * 8 + lane8;
    long long i10 = (bufb + y1 * WX + x0) * 8 + lane8;
    long long i11 = (bufb + y1 * WX + x1) * 8 + lane8;

    uint4 A  = __ldg(g_scr + i00);
    uint4 Bv = __ldg(g_scr + i10);
    uint4 Cv = __ldg(g_scr + i01);
    uint4 D  = __ldg(g_scr + i11);

    float r[8];
    const unsigned* au = (const unsigned*)&A;
    const unsigned* bu = (const unsigned*)&Bv;
    const unsigned* cu = (const unsigned*)&Cv;
    const unsigned* du = (const unsigned*)&D;
    #pragma unroll
    for (int j = 0; j < 4; j++) {
        float2 fa = __half22float2(*(const __half2*)&au[j]);
        float2 fb = __half22float2(*(const __half2*)&bu[j]);
        float2 fc = __half22float2(*(const __half2*)&cu[j]);
        float2 fd = __half22float2(*(const __half2*)&du[j]);
        r[2 * j + 0] = wa * fa.x + wb * fb.x + wc * fc.x + wd * fd.x;
        r[2 * j + 1] = wa * fa.y + wb * fb.y + wc * fc.y + wd * fd.y;
    }

    float4* o = (float4*)out;
    long long ob = pn * 16 + lane8 * 2;
    o[ob + 0] = make_float4(r[0], r[1], r[2], r[3]);
    o[ob + 1] = make_float4(r[4], r[5], r[6], r[7]);
}

// ---------------------------------------------------------------------------
__global__ void __launch_bounds__(256, 6)
fused_interp2(const float* __restrict__ x,
              const float* __restrict__ pos,
              const int* __restrict__ Hp,
              const int* __restrict__ Wp,
              float* __restrict__ out)
{
    __shared__ float tile[64 * 33];

    const int tid = threadIdx.x;
    const float Wf = (float)(*Wp);
    const float Hf = (float)(*Hp);

    for (int ph = 0; ph < NPHASE; ph++) {
        // Phase ph: transpose batches {2ph, 2ph+1} (if <16),
        //           gather    batches {2ph-2, 2ph-1} (if >=0).
        int nT = (ph < 8) ? 2 * CH_T : 0;
        int nG = (ph > 0) ? 2 * CH_G : 0;
        int nItems = nT + nG;

        for (int it = blockIdx.x; it < nItems; it += GRID_BLOCKS) {
            if (it < nT) {
                int b = 2 * ph + (it >= CH_T);
                do_transpose_chunk(x, b, it - (it >= CH_T ? CH_T : 0), tid, tile);
            } else {
                int g = it - nT;
                int b = 2 * (ph - 1) + (g >= CH_G);
                do_gather_chunk(pos, Wf, Hf, b, g - (g >= CH_G ? CH_G : 0), tid, out);
            }
        }

        // Grid barrier (skip after final phase). Monotone arrival counter:
        // phase ph complete when g_arrive reaches (ph+1)*GRID_BLOCKS.
        if (ph < NPHASE - 1) {
            __syncthreads();
            if (tid == 0) {
                __threadfence();                       // publish scratch writes
                atomicAdd(&g_arrive, 1u);
                unsigned target = (unsigned)(ph + 1) * GRID_BLOCKS;
                while (atomicAdd(&g_arrive, 0u) < target) __nanosleep(64);
                __threadfence();                       // acquire
            }
            __syncthreads();
        }
    }
}

extern "C" void kernel_launch(void* const* d_in, const int* in_sizes, int n_in,
                              void* d_out, int out_size)
{
    const float* x   = (const float*)d_in[0];
    const float* pos = (const float*)d_in[1];
    const int*   Hp  = (const int*)d_in[2];
    const int*   Wp  = (const int*)d_in[3];
    float* out = (float*)d_out;

    init_counters<<<1, 32>>>();
    fused_interp2<<<GRID_BLOCKS, 256>>>(x, pos, Hp, Wp, out);
}